// round 15
// baseline (speedup 1.0000x reference)
#include <cuda_runtime.h>
#include <cstdint>

// PQLayer forward on GB300 (sm_103a) — v14: v13 (best, 192.3us) with
// __launch_bounds__(128, 12) to lift occupancy (v13: regs=47 -> 10 blk/SM,
// occ 53%). Store stream unchanged: single-touch full-sector STG.256 rows.
//
// codes = stop_gradient(hard - soft) + soft == hard (one-hot) numerically.

#define BB 16384
#define MM 64
#define KK 256
#define DD 8
#define FEAT (MM * DD)          // 512
#define CHUNK_B 256             // b per block: 4 warps x 64 b (2 per lane)
#define NTHR 128

using u64 = unsigned long long;

__device__ __forceinline__ u64 pack2(float lo, float hi) {
    u64 r;
    uint32_t a = __float_as_uint(lo), b = __float_as_uint(hi);
    asm("mov.b64 %0, {%1, %2};" : "=l"(r) : "r"(a), "r"(b));
    return r;
}

__device__ __forceinline__ void unpack2(u64 v, float& lo, float& hi) {
    uint32_t a, b;
    asm("mov.b64 {%0, %1}, %2;" : "=r"(a), "=r"(b) : "l"(v));
    lo = __uint_as_float(a);
    hi = __uint_as_float(b);
}

// Packed dual fp32 FMA (Blackwell FFMA2): IEEE fp32 per lane.
__device__ __forceinline__ u64 fma2(u64 a, u64 b, u64 c) {
    u64 r;
    asm("fma.rn.f32x2 %0, %1, %2, %3;" : "=l"(r) : "l"(a), "l"(b), "l"(c));
    return r;
}

// 256-bit streaming store (full DRAM sector). sm_100+.
__device__ __forceinline__ void stg256_cs(float* p, float v0, float v1,
                                          float v2, float v3, float v4,
                                          float v5, float v6, float v7) {
    asm volatile("st.global.cs.v8.f32 [%0], {%1,%2,%3,%4,%5,%6,%7,%8};"
                 :: "l"(p), "f"(v0), "f"(v1), "f"(v2), "f"(v3),
                    "f"(v4), "f"(v5), "f"(v6), "f"(v7)
                 : "memory");
}

// 256-bit default store (for x_hat: stays cached, merges in L2).
__device__ __forceinline__ void stg256(float* p, const float4& a,
                                       const float4& b) {
    asm volatile("st.global.v8.f32 [%0], {%1,%2,%3,%4,%5,%6,%7,%8};"
                 :: "l"(p), "f"(a.x), "f"(a.y), "f"(a.z), "f"(a.w),
                    "f"(b.x), "f"(b.y), "f"(b.z), "f"(b.w)
                 : "memory");
}

__global__ void __launch_bounds__(NTHR, 12)
pq_forward_v14(const float* __restrict__ x, const float* __restrict__ C,
               float* __restrict__ xhat, float* __restrict__ codes)
{
    const int m    = blockIdx.x;
    const int tid  = threadIdx.x;
    const int lane = tid & 31;
    const int w    = tid >> 5;

    // cpk[j*8 + d] = { C[m][2j][d], C[m][2j+1][d] }  (k-pair packed, 8 KB)
    __shared__ __align__(16) u64    cpk[128 * 8];
    __shared__ __align__(16) float4 craw[KK * 2];    // raw copy for x_hat write

    {
        const float4* C4 = reinterpret_cast<const float4*>(C) + (size_t)m * (KK * 2);
#pragma unroll
        for (int q = tid; q < KK * 2; q += NTHR) {
            float4 f = C4[q];
            craw[q] = f;
            const int k = q >> 1, h = (q & 1) * 4;
            const int j = k >> 1, half = k & 1;
            float vals[4] = {f.x, f.y, f.z, f.w};
#pragma unroll
            for (int dd = 0; dd < 4; dd++)
                reinterpret_cast<uint32_t*>(&cpk[j * 8 + h + dd])[half] =
                    __float_as_uint(vals[dd]);
        }
    }
    __syncthreads();

    const int b0w = blockIdx.y * CHUNK_B + w * 64;   // warp's first b (owns 64)
    const int ba  = b0w + lane;                      // this thread's b #0
    const int bb  = b0w + 32 + lane;                 // this thread's b #1

    // ---- load x for both b's, duplicate-pack for f32x2 ----
    const float4* x4 = reinterpret_cast<const float4*>(x);
    const float4 a0 = x4[(size_t)ba * (FEAT / 4) + m * 2];
    const float4 a1 = x4[(size_t)ba * (FEAT / 4) + m * 2 + 1];
    const float4 q0 = x4[(size_t)bb * (FEAT / 4) + m * 2];
    const float4 q1 = x4[(size_t)bb * (FEAT / 4) + m * 2 + 1];
    u64 xpa[8], xpb[8];
    xpa[0] = pack2(a0.x, a0.x); xpa[1] = pack2(a0.y, a0.y);
    xpa[2] = pack2(a0.z, a0.z); xpa[3] = pack2(a0.w, a0.w);
    xpa[4] = pack2(a1.x, a1.x); xpa[5] = pack2(a1.y, a1.y);
    xpa[6] = pack2(a1.z, a1.z); xpa[7] = pack2(a1.w, a1.w);
    xpb[0] = pack2(q0.x, q0.x); xpb[1] = pack2(q0.y, q0.y);
    xpb[2] = pack2(q0.z, q0.z); xpb[3] = pack2(q0.w, q0.w);
    xpb[4] = pack2(q1.x, q1.x); xpb[5] = pack2(q1.y, q1.y);
    xpb[6] = pack2(q1.z, q1.z); xpb[7] = pack2(q1.w, q1.w);

    // ---- argmax over 256 codewords for BOTH b's: shared LDS stream ----
    float bva = -3.402823466e+38f, bvb = -3.402823466e+38f;
    int   bka = 0, bkb = 0;
#pragma unroll 4
    for (int j = 0; j < 128; j++) {
        const ulonglong2* cj = reinterpret_cast<const ulonglong2*>(&cpk[j * 8]);
        ulonglong2 c01 = cj[0], c23 = cj[1], c45 = cj[2], c67 = cj[3];

        u64 acca = 0ull, accb = 0ull;   // d-sequential fp32 accumulation
        acca = fma2(c01.x, xpa[0], acca);  accb = fma2(c01.x, xpb[0], accb);
        acca = fma2(c01.y, xpa[1], acca);  accb = fma2(c01.y, xpb[1], accb);
        acca = fma2(c23.x, xpa[2], acca);  accb = fma2(c23.x, xpb[2], accb);
        acca = fma2(c23.y, xpa[3], acca);  accb = fma2(c23.y, xpb[3], accb);
        acca = fma2(c45.x, xpa[4], acca);  accb = fma2(c45.x, xpb[4], accb);
        acca = fma2(c45.y, xpa[5], acca);  accb = fma2(c45.y, xpb[5], accb);
        acca = fma2(c67.x, xpa[6], acca);  accb = fma2(c67.x, xpb[6], accb);
        acca = fma2(c67.y, xpa[7], acca);  accb = fma2(c67.y, xpb[7], accb);

        float lo, hi;
        unpack2(acca, lo, hi);
        if (lo > bva) { bva = lo; bka = 2 * j; }     // strict >: lowest k ties
        if (hi > bva) { bva = hi; bka = 2 * j + 1; }
        unpack2(accb, lo, hi);
        if (lo > bvb) { bvb = lo; bkb = 2 * j; }
        if (hi > bvb) { bvb = hi; bkb = 2 * j + 1; }
    }

    // ---- x_hat: one 32B-sector STG.256 per lane per b (no RMW) ----
    {
        float* xh = xhat;
        stg256(xh + (size_t)ba * FEAT + m * 8, craw[bka * 2], craw[bka * 2 + 1]);
        stg256(xh + (size_t)bb * FEAT + m * 8, craw[bkb * 2], craw[bkb * 2 + 1]);
    }

    // ---- fused one-hot stream: 64 rows, each written ONCE, coalesced ----
    // Row r: winner bka of lane r; row r+32: winner bkb of lane r.
    // Each lane covers k [8*lane, 8*lane+8) with ONE full-sector STG.256.
    {
        const uint32_t packed = (uint32_t)bka | ((uint32_t)bkb << 8);
        float* crow = codes + ((size_t)b0w * MM + m) * KK + lane * 8;
        const size_t rsf = (size_t)MM * KK;          // floats per b-row
        const int k0 = 8 * lane;
#pragma unroll 8
        for (int r = 0; r < 32; r++) {
            const uint32_t pk = __shfl_sync(0xffffffffu, packed, r);
            const int oa = (int)(pk & 0xffu) - k0;       // winner rel. offset
            const int ob = (int)((pk >> 8) & 0xffu) - k0;
            stg256_cs(crow,
                      oa == 0 ? 1.f : 0.f, oa == 1 ? 1.f : 0.f,
                      oa == 2 ? 1.f : 0.f, oa == 3 ? 1.f : 0.f,
                      oa == 4 ? 1.f : 0.f, oa == 5 ? 1.f : 0.f,
                      oa == 6 ? 1.f : 0.f, oa == 7 ? 1.f : 0.f);
            stg256_cs(crow + 32 * rsf,                   // row r+32 (b #1)
                      ob == 0 ? 1.f : 0.f, ob == 1 ? 1.f : 0.f,
                      ob == 2 ? 1.f : 0.f, ob == 3 ? 1.f : 0.f,
                      ob == 4 ? 1.f : 0.f, ob == 5 ? 1.f : 0.f,
                      ob == 6 ? 1.f : 0.f, ob == 7 ? 1.f : 0.f);
            crow += rsf;                  // next b, same m
        }
    }
}

extern "C" void kernel_launch(void* const* d_in, const int* in_sizes, int n_in,
                              void* d_out, int out_size)
{
    const float* x = (const float*)d_in[0];
    const float* C = (const float*)d_in[1];
    if (n_in >= 2 && in_sizes[0] == MM * KK * DD && in_sizes[1] == BB * FEAT) {
        x = (const float*)d_in[1];
        C = (const float*)d_in[0];
    }

    const long XHAT_N  = (long)BB * FEAT;        // 8,388,608
    const long CODES_N = (long)BB * MM * KK;     // 268,435,456

    float* xhat  = nullptr;
    float* codes = nullptr;
    if ((long)out_size >= XHAT_N + CODES_N) {
        xhat  = (float*)d_out;
        codes = (float*)d_out + XHAT_N;
    } else if ((long)out_size == CODES_N) {
        codes = (float*)d_out;
    } else {
        xhat = (float*)d_out;
    }

    dim3 grid(MM, BB / CHUNK_B);                 // (64, 64) = 4096 blocks
    pq_forward_v14<<<grid, NTHR>>>(x, C, xhat, codes);
}

// round 16
// speedup vs baseline: 1.0393x; 1.0393x over previous
#include <cuda_runtime.h>
#include <cstdint>

// PQLayer forward on GB300 (sm_103a) — v15: v13 (best, 192.3us: STG.256
// full-sector one-hot rows, m-major, single-touch) with the x LDGs hoisted
// above __syncthreads so their DRAM latency overlaps C staging. Store stream
// byte-identical to v13. (v14 proved forcing occupancy hurts: regs 47->40
// degraded scheduling; keep natural regalloc.)
//
// codes = stop_gradient(hard - soft) + soft == hard (one-hot) numerically.

#define BB 16384
#define MM 64
#define KK 256
#define DD 8
#define FEAT (MM * DD)          // 512
#define CHUNK_B 256             // b per block: 4 warps x 64 b (2 per lane)
#define NTHR 128

using u64 = unsigned long long;

__device__ __forceinline__ u64 pack2(float lo, float hi) {
    u64 r;
    uint32_t a = __float_as_uint(lo), b = __float_as_uint(hi);
    asm("mov.b64 %0, {%1, %2};" : "=l"(r) : "r"(a), "r"(b));
    return r;
}

__device__ __forceinline__ void unpack2(u64 v, float& lo, float& hi) {
    uint32_t a, b;
    asm("mov.b64 {%0, %1}, %2;" : "=r"(a), "=r"(b) : "l"(v));
    lo = __uint_as_float(a);
    hi = __uint_as_float(b);
}

// Packed dual fp32 FMA (Blackwell FFMA2): IEEE fp32 per lane.
__device__ __forceinline__ u64 fma2(u64 a, u64 b, u64 c) {
    u64 r;
    asm("fma.rn.f32x2 %0, %1, %2, %3;" : "=l"(r) : "l"(a), "l"(b), "l"(c));
    return r;
}

// 256-bit streaming store (full DRAM sector). sm_100+.
__device__ __forceinline__ void stg256_cs(float* p, float v0, float v1,
                                          float v2, float v3, float v4,
                                          float v5, float v6, float v7) {
    asm volatile("st.global.cs.v8.f32 [%0], {%1,%2,%3,%4,%5,%6,%7,%8};"
                 :: "l"(p), "f"(v0), "f"(v1), "f"(v2), "f"(v3),
                    "f"(v4), "f"(v5), "f"(v6), "f"(v7)
                 : "memory");
}

// 256-bit default store (for x_hat: stays cached, merges in L2).
__device__ __forceinline__ void stg256(float* p, const float4& a,
                                       const float4& b) {
    asm volatile("st.global.v8.f32 [%0], {%1,%2,%3,%4,%5,%6,%7,%8};"
                 :: "l"(p), "f"(a.x), "f"(a.y), "f"(a.z), "f"(a.w),
                    "f"(b.x), "f"(b.y), "f"(b.z), "f"(b.w)
                 : "memory");
}

__global__ void __launch_bounds__(NTHR)
pq_forward_v15(const float* __restrict__ x, const float* __restrict__ C,
               float* __restrict__ xhat, float* __restrict__ codes)
{
    const int m    = blockIdx.x;
    const int tid  = threadIdx.x;
    const int lane = tid & 31;
    const int w    = tid >> 5;

    // cpk[j*8 + d] = { C[m][2j][d], C[m][2j+1][d] }  (k-pair packed, 8 KB)
    __shared__ __align__(16) u64    cpk[128 * 8];
    __shared__ __align__(16) float4 craw[KK * 2];    // raw copy for x_hat write

    const int b0w = blockIdx.y * CHUNK_B + w * 64;   // warp's first b (owns 64)
    const int ba  = b0w + lane;                      // this thread's b #0
    const int bb  = b0w + 32 + lane;                 // this thread's b #1

    // ---- issue x loads FIRST: latency overlaps C staging + barrier ----
    const float4* x4 = reinterpret_cast<const float4*>(x);
    const float4 a0 = x4[(size_t)ba * (FEAT / 4) + m * 2];
    const float4 a1 = x4[(size_t)ba * (FEAT / 4) + m * 2 + 1];
    const float4 q0 = x4[(size_t)bb * (FEAT / 4) + m * 2];
    const float4 q1 = x4[(size_t)bb * (FEAT / 4) + m * 2 + 1];

    // ---- stage C[m] (8 KB, coalesced) into both smem views ----
    {
        const float4* C4 = reinterpret_cast<const float4*>(C) + (size_t)m * (KK * 2);
#pragma unroll
        for (int q = tid; q < KK * 2; q += NTHR) {
            float4 f = C4[q];
            craw[q] = f;
            const int k = q >> 1, h = (q & 1) * 4;
            const int j = k >> 1, half = k & 1;
            float vals[4] = {f.x, f.y, f.z, f.w};
#pragma unroll
            for (int dd = 0; dd < 4; dd++)
                reinterpret_cast<uint32_t*>(&cpk[j * 8 + h + dd])[half] =
                    __float_as_uint(vals[dd]);
        }
    }
    __syncthreads();

    // ---- duplicate-pack x for f32x2 ----
    u64 xpa[8], xpb[8];
    xpa[0] = pack2(a0.x, a0.x); xpa[1] = pack2(a0.y, a0.y);
    xpa[2] = pack2(a0.z, a0.z); xpa[3] = pack2(a0.w, a0.w);
    xpa[4] = pack2(a1.x, a1.x); xpa[5] = pack2(a1.y, a1.y);
    xpa[6] = pack2(a1.z, a1.z); xpa[7] = pack2(a1.w, a1.w);
    xpb[0] = pack2(q0.x, q0.x); xpb[1] = pack2(q0.y, q0.y);
    xpb[2] = pack2(q0.z, q0.z); xpb[3] = pack2(q0.w, q0.w);
    xpb[4] = pack2(q1.x, q1.x); xpb[5] = pack2(q1.y, q1.y);
    xpb[6] = pack2(q1.z, q1.z); xpb[7] = pack2(q1.w, q1.w);

    // ---- argmax over 256 codewords for BOTH b's: shared LDS stream ----
    float bva = -3.402823466e+38f, bvb = -3.402823466e+38f;
    int   bka = 0, bkb = 0;
#pragma unroll 4
    for (int j = 0; j < 128; j++) {
        const ulonglong2* cj = reinterpret_cast<const ulonglong2*>(&cpk[j * 8]);
        ulonglong2 c01 = cj[0], c23 = cj[1], c45 = cj[2], c67 = cj[3];

        u64 acca = 0ull, accb = 0ull;   // d-sequential fp32 accumulation
        acca = fma2(c01.x, xpa[0], acca);  accb = fma2(c01.x, xpb[0], accb);
        acca = fma2(c01.y, xpa[1], acca);  accb = fma2(c01.y, xpb[1], accb);
        acca = fma2(c23.x, xpa[2], acca);  accb = fma2(c23.x, xpb[2], accb);
        acca = fma2(c23.y, xpa[3], acca);  accb = fma2(c23.y, xpb[3], accb);
        acca = fma2(c45.x, xpa[4], acca);  accb = fma2(c45.x, xpb[4], accb);
        acca = fma2(c45.y, xpa[5], acca);  accb = fma2(c45.y, xpb[5], accb);
        acca = fma2(c67.x, xpa[6], acca);  accb = fma2(c67.x, xpb[6], accb);
        acca = fma2(c67.y, xpa[7], acca);  accb = fma2(c67.y, xpb[7], accb);

        float lo, hi;
        unpack2(acca, lo, hi);
        if (lo > bva) { bva = lo; bka = 2 * j; }     // strict >: lowest k ties
        if (hi > bva) { bva = hi; bka = 2 * j + 1; }
        unpack2(accb, lo, hi);
        if (lo > bvb) { bvb = lo; bkb = 2 * j; }
        if (hi > bvb) { bvb = hi; bkb = 2 * j + 1; }
    }

    // ---- x_hat: one 32B-sector STG.256 per lane per b (no RMW) ----
    {
        float* xh = xhat;
        stg256(xh + (size_t)ba * FEAT + m * 8, craw[bka * 2], craw[bka * 2 + 1]);
        stg256(xh + (size_t)bb * FEAT + m * 8, craw[bkb * 2], craw[bkb * 2 + 1]);
    }

    // ---- fused one-hot stream: 64 rows, each written ONCE, coalesced ----
    // Row r: winner bka of lane r; row r+32: winner bkb of lane r.
    // Each lane covers k [8*lane, 8*lane+8) with ONE full-sector STG.256.
    {
        const uint32_t packed = (uint32_t)bka | ((uint32_t)bkb << 8);
        float* crow = codes + ((size_t)b0w * MM + m) * KK + lane * 8;
        const size_t rsf = (size_t)MM * KK;          // floats per b-row
        const int k0 = 8 * lane;
#pragma unroll 8
        for (int r = 0; r < 32; r++) {
            const uint32_t pk = __shfl_sync(0xffffffffu, packed, r);
            const int oa = (int)(pk & 0xffu) - k0;       // winner rel. offset
            const int ob = (int)((pk >> 8) & 0xffu) - k0;
            stg256_cs(crow,
                      oa == 0 ? 1.f : 0.f, oa == 1 ? 1.f : 0.f,
                      oa == 2 ? 1.f : 0.f, oa == 3 ? 1.f : 0.f,
                      oa == 4 ? 1.f : 0.f, oa == 5 ? 1.f : 0.f,
                      oa == 6 ? 1.f : 0.f, oa == 7 ? 1.f : 0.f);
            stg256_cs(crow + 32 * rsf,                   // row r+32 (b #1)
                      ob == 0 ? 1.f : 0.f, ob == 1 ? 1.f : 0.f,
                      ob == 2 ? 1.f : 0.f, ob == 3 ? 1.f : 0.f,
                      ob == 4 ? 1.f : 0.f, ob == 5 ? 1.f : 0.f,
                      ob == 6 ? 1.f : 0.f, ob == 7 ? 1.f : 0.f);
            crow += rsf;                  // next b, same m
        }
    }
}

extern "C" void kernel_launch(void* const* d_in, const int* in_sizes, int n_in,
                              void* d_out, int out_size)
{
    const float* x = (const float*)d_in[0];
    const float* C = (const float*)d_in[1];
    if (n_in >= 2 && in_sizes[0] == MM * KK * DD && in_sizes[1] == BB * FEAT) {
        x = (const float*)d_in[1];
        C = (const float*)d_in[0];
    }

    const long XHAT_N  = (long)BB * FEAT;        // 8,388,608
    const long CODES_N = (long)BB * MM * KK;     // 268,435,456

    float* xhat  = nullptr;
    float* codes = nullptr;
    if ((long)out_size >= XHAT_N + CODES_N) {
        xhat  = (float*)d_out;
        codes = (float*)d_out + XHAT_N;
    } else if ((long)out_size == CODES_N) {
        codes = (float*)d_out;
    } else {
        xhat = (float*)d_out;
    }

    dim3 grid(MM, BB / CHUNK_B);                 // (64, 64) = 4096 blocks
    pq_forward_v15<<<grid, NTHR>>>(x, C, xhat, codes);
}